// round 1
// baseline (speedup 1.0000x reference)
#include <cuda_runtime.h>

#define DIM 128
#define D2  256

__device__ __forceinline__ float prelu_f(float x, float a) {
    return x >= 0.0f ? x : a * x;
}

// Bilinear for a single node: out = bias + sum_v vec[v] * sum_d x[d]*W[k,d,v]
// x = concat(xlo, xhi), each DIM floats in shared memory (broadcast reads).
__device__ __forceinline__ float bilinear_one(
    const float* __restrict__ W,   // [DIM, D2, 3]
    int k,
    const float* __restrict__ xlo,
    const float* __restrict__ xhi,
    const float* __restrict__ v3,  // 3 floats (global)
    float bias)
{
    float a0 = 0.f, a1 = 0.f, a2 = 0.f;
    const float* Wr = W + (long)k * D2 * 3;
    #pragma unroll 4
    for (int d = 0; d < DIM; d++) {
        float xd = xlo[d];
        a0 = fmaf(xd, Wr[d * 3 + 0], a0);
        a1 = fmaf(xd, Wr[d * 3 + 1], a1);
        a2 = fmaf(xd, Wr[d * 3 + 2], a2);
    }
    const float* Wr2 = Wr + DIM * 3;
    #pragma unroll 4
    for (int d = 0; d < DIM; d++) {
        float xd = xhi[d];
        a0 = fmaf(xd, Wr2[d * 3 + 0], a0);
        a1 = fmaf(xd, Wr2[d * 3 + 1], a1);
        a2 = fmaf(xd, Wr2[d * 3 + 2], a2);
    }
    return bias + a0 * v3[0] + a1 * v3[1] + a2 * v3[2];
}

// Linear: out = bias + concat(xlo, xhi) . W[k, :]
__device__ __forceinline__ float linear_one(
    const float* __restrict__ W,   // [DIM, D2]
    int k,
    const float* __restrict__ xlo,
    const float* __restrict__ xhi,
    float bias)
{
    float acc = bias;
    const float* Wr = W + (long)k * D2;
    #pragma unroll 4
    for (int d = 0; d < DIM; d++) acc = fmaf(xlo[d], Wr[d], acc);
    #pragma unroll 4
    for (int d = 0; d < DIM; d++) acc = fmaf(xhi[d], Wr[DIM + d], acc);
    return acc;
}

__global__ __launch_bounds__(DIM) void encoder_cone_kernel(
    const float* __restrict__ points,  // [B, N3, 3]
    const float* __restrict__ vec2,    // [B, N2, 3]
    const float* __restrict__ vec1,    // [B, N1, 3]
    const float* __restrict__ vec0,    // [B, 1, 3]
    const float* __restrict__ Wp,      // [DIM, 3]
    const float* __restrict__ bp,      // [DIM]
    const float* __restrict__ a_leaf,  // scalar
    const float* __restrict__ Wb2,     // [DIM, D2, 3]
    const float* __restrict__ bb2,     // [DIM]
    const float* __restrict__ a2p,     // scalar
    const float* __restrict__ Wb1,     // [DIM, D2, 3]
    const float* __restrict__ bb1,     // [DIM]
    const float* __restrict__ Ws1,     // [DIM, D2]
    const float* __restrict__ bs1,     // [DIM]
    const float* __restrict__ a1p,     // scalar
    const float* __restrict__ Wb0,     // [DIM, D2, 3]
    const float* __restrict__ bb0,     // [DIM]
    const float* __restrict__ Ws0,     // [DIM, D2]
    const float* __restrict__ bs0,     // [DIM]
    const float* __restrict__ a0p,     // scalar
    const int* __restrict__ cl2, const int* __restrict__ cr2,
    const int* __restrict__ cl1, const int* __restrict__ cr1,
    const int* __restrict__ cs1,
    const int* __restrict__ cl0, const int* __restrict__ cr0,
    const int* __restrict__ cs0,
    float* __restrict__ out,           // [B, DIM]
    int N3, int N2n, int N1n)
{
    const int b = blockIdx.x;
    const int k = threadIdx.x;

    __shared__ float leaf[12][DIM];  // h3 rows actually needed
    __shared__ float h2s[5][DIM];    // h2 rows actually needed
    __shared__ float h1s[2][DIM];    // h1 rows actually needed
    __shared__ float tbuf[DIM];      // bilinear intermediate

    // ---- Resolve the dependency cone (same for every batch; broadcast loads) ----
    const int l1a = cl0[0];
    const int l1b = cr0[0];

    int n2[5];
    n2[0] = cl1[l1a]; n2[1] = cr1[l1a];
    n2[2] = cl1[l1b]; n2[3] = cr1[l1b];
    n2[4] = cs0[0];

    int p[12];
    #pragma unroll
    for (int j = 0; j < 5; j++) {
        p[2 * j]     = cl2[n2[j]];
        p[2 * j + 1] = cr2[n2[j]];
    }
    p[10] = cs1[l1a];
    p[11] = cs1[l1b];

    const float AL = a_leaf[0], A2 = a2p[0], A1 = a1p[0], A0 = a0p[0];

    // ---- Leaf layer: 12 rows of h3 = prelu(points @ Wp^T + bp) ----
    {
        const float w0 = Wp[k * 3 + 0];
        const float w1 = Wp[k * 3 + 1];
        const float w2 = Wp[k * 3 + 2];
        const float bk = bp[k];
        #pragma unroll
        for (int j = 0; j < 12; j++) {
            const float* pt = points + ((long)b * N3 + p[j]) * 3;
            float h = fmaf(w0, pt[0], fmaf(w1, pt[1], fmaf(w2, pt[2], bk)));
            leaf[j][k] = prelu_f(h, AL);
        }
    }
    __syncthreads();

    // ---- Layer 2: 5 nodes, fused so each Wb2 row is streamed once ----
    {
        float acc[5][3];
        #pragma unroll
        for (int j = 0; j < 5; j++) {
            acc[j][0] = 0.f; acc[j][1] = 0.f; acc[j][2] = 0.f;
        }
        const float* Wr = Wb2 + (long)k * D2 * 3;
        #pragma unroll 4
        for (int d = 0; d < DIM; d++) {
            const float wv0 = Wr[d * 3 + 0];
            const float wv1 = Wr[d * 3 + 1];
            const float wv2 = Wr[d * 3 + 2];
            #pragma unroll
            for (int j = 0; j < 5; j++) {
                const float xd = leaf[2 * j][d];
                acc[j][0] = fmaf(xd, wv0, acc[j][0]);
                acc[j][1] = fmaf(xd, wv1, acc[j][1]);
                acc[j][2] = fmaf(xd, wv2, acc[j][2]);
            }
        }
        const float* Wr2 = Wr + DIM * 3;
        #pragma unroll 4
        for (int d = 0; d < DIM; d++) {
            const float wv0 = Wr2[d * 3 + 0];
            const float wv1 = Wr2[d * 3 + 1];
            const float wv2 = Wr2[d * 3 + 2];
            #pragma unroll
            for (int j = 0; j < 5; j++) {
                const float xd = leaf[2 * j + 1][d];
                acc[j][0] = fmaf(xd, wv0, acc[j][0]);
                acc[j][1] = fmaf(xd, wv1, acc[j][1]);
                acc[j][2] = fmaf(xd, wv2, acc[j][2]);
            }
        }
        const float bbk = bb2[k];
        #pragma unroll
        for (int j = 0; j < 5; j++) {
            const float* v = vec2 + ((long)b * N2n + n2[j]) * 3;
            float z = bbk + acc[j][0] * v[0] + acc[j][1] * v[1] + acc[j][2] * v[2];
            h2s[j][k] = prelu_f(z, A2);
        }
    }
    __syncthreads();

    // ---- Layer 1: 2 nodes, bilinear then sample-merge linear ----
    for (int m = 0; m < 2; m++) {
        const int node = (m == 0) ? l1a : l1b;
        const float* v = vec1 + ((long)b * N1n + node) * 3;
        float z = bilinear_one(Wb1, k, h2s[2 * m], h2s[2 * m + 1], v, bb1[k]);
        tbuf[k] = prelu_f(z, A1);
        __syncthreads();
        float y = linear_one(Ws1, k, tbuf, leaf[10 + m], bs1[k]);
        h1s[m][k] = prelu_f(y, A1);
        __syncthreads();  // protect tbuf before next iteration reuses it
    }

    // ---- Layer 0 (root): bilinear then sample-merge linear ----
    {
        const float* v = vec0 + (long)b * 3;
        float z = bilinear_one(Wb0, k, h1s[0], h1s[1], v, bb0[k]);
        tbuf[k] = prelu_f(z, A0);
        __syncthreads();
        float y = linear_one(Ws0, k, tbuf, h2s[4], bs0[k]);
        out[(long)b * DIM + k] = prelu_f(y, A0);
    }
}

extern "C" void kernel_launch(void* const* d_in, const int* in_sizes, int n_in,
                              void* d_out, int out_size)
{
    const float* points = (const float*)d_in[0];
    const float* vec2   = (const float*)d_in[1];
    const float* vec1   = (const float*)d_in[2];
    const float* vec0   = (const float*)d_in[3];
    const float* Wp     = (const float*)d_in[4];
    const float* bp     = (const float*)d_in[5];
    const float* a_leaf = (const float*)d_in[6];
    const float* Wb2    = (const float*)d_in[7];
    const float* bb2    = (const float*)d_in[8];
    const float* a2     = (const float*)d_in[9];
    const float* Wb1    = (const float*)d_in[10];
    const float* bb1    = (const float*)d_in[11];
    const float* Ws1    = (const float*)d_in[12];
    const float* bs1    = (const float*)d_in[13];
    const float* a1     = (const float*)d_in[14];
    const float* Wb0    = (const float*)d_in[15];
    const float* bb0    = (const float*)d_in[16];
    const float* Ws0    = (const float*)d_in[17];
    const float* bs0    = (const float*)d_in[18];
    const float* a0     = (const float*)d_in[19];
    const int*   cl2    = (const int*)d_in[20];
    const int*   cr2    = (const int*)d_in[21];
    const int*   cl1    = (const int*)d_in[22];
    const int*   cr1    = (const int*)d_in[23];
    const int*   cs1    = (const int*)d_in[24];
    const int*   cl0    = (const int*)d_in[25];
    const int*   cr0    = (const int*)d_in[26];
    const int*   cs0    = (const int*)d_in[27];

    const int B  = out_size / DIM;          // 8
    const int N3 = in_sizes[0] / (3 * B);   // 131072
    const int N2 = in_sizes[1] / (3 * B);   // 65536
    const int N1 = in_sizes[2] / (3 * B);   // 1024

    encoder_cone_kernel<<<B, DIM>>>(
        points, vec2, vec1, vec0,
        Wp, bp, a_leaf, Wb2, bb2, a2,
        Wb1, bb1, Ws1, bs1, a1,
        Wb0, bb0, Ws0, bs0, a0,
        cl2, cr2, cl1, cr1, cs1, cl0, cr0, cs0,
        (float*)d_out, N3, N2, N1);
}

// round 2
// speedup vs baseline: 7.1847x; 7.1847x over previous
#include <cuda_runtime.h>

#define DIM 128
#define D2  256
#define NTHREADS 1024

__device__ __forceinline__ float prelu_f(float x, float a) {
    return x >= 0.0f ? x : a * x;
}

__device__ __forceinline__ float wred(float v) {
    v += __shfl_xor_sync(0xffffffffu, v, 16);
    v += __shfl_xor_sync(0xffffffffu, v, 8);
    v += __shfl_xor_sync(0xffffffffu, v, 4);
    v += __shfl_xor_sync(0xffffffffu, v, 2);
    v += __shfl_xor_sync(0xffffffffu, v, 1);
    return v;
}

__device__ __forceinline__ float dot4(float4 a, float4 b) {
    return fmaf(a.x, b.x, fmaf(a.y, b.y, fmaf(a.z, b.z, a.w * b.w)));
}

__global__ __launch_bounds__(NTHREADS) void encoder_cone_kernel(
    const float* __restrict__ points,  // [B, N3, 3]
    const float* __restrict__ vec2,    // [B, N2, 3]
    const float* __restrict__ vec1,    // [B, N1, 3]
    const float* __restrict__ vec0,    // [B, 1, 3]
    const float* __restrict__ Wp,      // [DIM, 3]
    const float* __restrict__ bp,      // [DIM]
    const float* __restrict__ a_leaf,
    const float* __restrict__ Wb2,     // [DIM, D2, 3] = [DIM, 768]
    const float* __restrict__ bb2,
    const float* __restrict__ a2p,
    const float* __restrict__ Wb1,     // [DIM, 768]
    const float* __restrict__ bb1,
    const float* __restrict__ Ws1,     // [DIM, D2]
    const float* __restrict__ bs1,
    const float* __restrict__ a1p,
    const float* __restrict__ Wb0,     // [DIM, 768]
    const float* __restrict__ bb0,
    const float* __restrict__ Ws0,     // [DIM, D2]
    const float* __restrict__ bs0,
    const float* __restrict__ a0p,
    const int* __restrict__ cl2, const int* __restrict__ cr2,
    const int* __restrict__ cl1, const int* __restrict__ cr1,
    const int* __restrict__ cs1,
    const int* __restrict__ cl0, const int* __restrict__ cr0,
    const int* __restrict__ cs0,
    float* __restrict__ out,           // [B, DIM]
    int N3, int N2n, int N1n)
{
    const int b   = blockIdx.x;
    const int tid = threadIdx.x;
    const int w   = tid >> 5;
    const int l   = tid & 31;

    __shared__ __align__(16) float leaf[12][DIM];  // needed h3 rows
    __shared__ __align__(16) float h2s[5][DIM];    // needed h2 rows
    __shared__ __align__(16) float h1s[2][DIM];    // needed h1 rows
    __shared__ __align__(16) float tb[2][DIM];     // L1 bilinear outputs
    __shared__ __align__(16) float tb0[DIM];       // root bilinear output
    __shared__ __align__(16) float z2[5][768];     // flattened bilinear operands
    __shared__ __align__(16) float z1[2][768];
    __shared__ __align__(16) float z0[768];
    __shared__ int sp[12];   // leaf indices
    __shared__ int sn2[5];   // layer-2 node indices
    __shared__ int sl1[2];   // layer-1 node indices

    const float AL = a_leaf[0], A2 = a2p[0], A1 = a1p[0], A0 = a0p[0];

    // ---- Resolve the dependency cone (thread 0, dependent load chain) ----
    if (tid == 0) {
        int l1a = cl0[0];
        int l1b = cr0[0];
        sl1[0] = l1a; sl1[1] = l1b;
        int n0 = cl1[l1a], n1 = cr1[l1a], n2_ = cl1[l1b], n3 = cr1[l1b], n4 = cs0[0];
        sn2[0] = n0; sn2[1] = n1; sn2[2] = n2_; sn2[3] = n3; sn2[4] = n4;
        sp[0] = cl2[n0];  sp[1] = cr2[n0];
        sp[2] = cl2[n1];  sp[3] = cr2[n1];
        sp[4] = cl2[n2_]; sp[5] = cr2[n2_];
        sp[6] = cl2[n3];  sp[7] = cr2[n3];
        sp[8] = cl2[n4];  sp[9] = cr2[n4];
        sp[10] = cs1[l1a]; sp[11] = cs1[l1b];
    }
    __syncthreads();

    // ---- Leaf layer: 12 rows of h3 = prelu(points @ Wp^T + bp) ----
    for (int i = tid; i < 12 * DIM; i += NTHREADS) {
        int j = i >> 7, k = i & 127;
        const float* pt = points + ((long)b * N3 + sp[j]) * 3;
        float h = fmaf(Wp[k * 3 + 0], pt[0],
                  fmaf(Wp[k * 3 + 1], pt[1],
                  fmaf(Wp[k * 3 + 2], pt[2], bp[k])));
        leaf[j][k] = prelu_f(h, AL);
    }
    __syncthreads();

    // ---- Build z2[j][e] = xcat_j[e/3] * vec2_j[e%3] ----
    for (int i = tid; i < 5 * 768; i += NTHREADS) {
        int j = i / 768;
        int e = i - j * 768;
        unsigned d = (unsigned)e / 3u;
        int v = e - 3 * (int)d;
        float x = leaf[2 * j + (d >> 7)][d & 127];
        float vv = vec2[((long)b * N2n + sn2[j]) * 3 + v];
        z2[j][e] = x * vv;
    }
    __syncthreads();

    // ---- Layer 2: 5 nodes fused, warp-per-k dot products ----
    {
        #pragma unroll
        for (int kk = 0; kk < 4; kk++) {
            int k = (w << 2) + kk;
            const float4* Wr = (const float4*)Wb2 + (long)k * 192;
            float acc[5] = {0.f, 0.f, 0.f, 0.f, 0.f};
            #pragma unroll
            for (int t = 0; t < 6; t++) {
                float4 wv = Wr[t * 32 + l];
                #pragma unroll
                for (int j = 0; j < 5; j++) {
                    float4 zz = ((const float4*)z2[j])[t * 32 + l];
                    acc[j] = fmaf(wv.x, zz.x,
                             fmaf(wv.y, zz.y,
                             fmaf(wv.z, zz.z,
                             fmaf(wv.w, zz.w, acc[j]))));
                }
            }
            #pragma unroll
            for (int j = 0; j < 5; j++) {
                float s = wred(acc[j]);
                if (l == 0) h2s[j][k] = prelu_f(s + bb2[k], A2);
            }
        }
    }
    __syncthreads();

    // ---- Build z1[j][e] from h2 pairs + vec1 ----
    for (int i = tid; i < 2 * 768; i += NTHREADS) {
        int j = i >= 768 ? 1 : 0;
        int e = i - j * 768;
        unsigned d = (unsigned)e / 3u;
        int v = e - 3 * (int)d;
        float x = h2s[2 * j + (d >> 7)][d & 127];
        float vv = vec1[((long)b * N1n + sl1[j]) * 3 + v];
        z1[j][e] = x * vv;
    }
    __syncthreads();

    // ---- Layer 1 bilinear: 2 nodes x 128 k = 256 warp-dots ----
    {
        #pragma unroll
        for (int jj = 0; jj < 8; jj++) {
            int idx = (w << 3) + jj;
            int j = idx >> 7;
            int k = idx & 127;
            const float4* Wr = (const float4*)Wb1 + (long)k * 192;
            const float4* zr = (const float4*)z1[j];
            float acc = 0.f;
            #pragma unroll
            for (int t = 0; t < 6; t++)
                acc += dot4(Wr[t * 32 + l], zr[t * 32 + l]);
            float s = wred(acc);
            if (l == 0) tb[j][k] = prelu_f(s + bb1[k], A1);
        }
    }
    __syncthreads();

    // ---- Layer 1 sample-merge linear: x = concat(tb[j], leaf[10+j]) ----
    {
        #pragma unroll
        for (int jj = 0; jj < 8; jj++) {
            int idx = (w << 3) + jj;
            int j = idx >> 7;
            int k = idx & 127;
            const float4* Wr = (const float4*)Ws1 + (long)k * 64;
            float acc = dot4(Wr[l],      ((const float4*)tb[j])[l]);
            acc      += dot4(Wr[32 + l], ((const float4*)leaf[10 + j])[l]);
            float s = wred(acc);
            if (l == 0) h1s[j][k] = prelu_f(s + bs1[k], A1);
        }
    }
    __syncthreads();

    // ---- Build z0 from h1 pair + vec0 ----
    if (tid < 768) {
        int e = tid;
        unsigned d = (unsigned)e / 3u;
        int v = e - 3 * (int)d;
        float x = h1s[d >> 7][d & 127];
        z0[e] = x * vec0[(long)b * 3 + v];
    }
    __syncthreads();

    // ---- Root bilinear: 128 warp-dots ----
    {
        #pragma unroll
        for (int kk = 0; kk < 4; kk++) {
            int k = (w << 2) + kk;
            const float4* Wr = (const float4*)Wb0 + (long)k * 192;
            float acc = 0.f;
            #pragma unroll
            for (int t = 0; t < 6; t++)
                acc += dot4(Wr[t * 32 + l], ((const float4*)z0)[t * 32 + l]);
            float s = wred(acc);
            if (l == 0) tb0[k] = prelu_f(s + bb0[k], A0);
        }
    }
    __syncthreads();

    // ---- Root linear: x = concat(tb0, h2s[4]) ----
    {
        #pragma unroll
        for (int kk = 0; kk < 4; kk++) {
            int k = (w << 2) + kk;
            const float4* Wr = (const float4*)Ws0 + (long)k * 64;
            float acc = dot4(Wr[l],      ((const float4*)tb0)[l]);
            acc      += dot4(Wr[32 + l], ((const float4*)h2s[4])[l]);
            float s = wred(acc);
            if (l == 0) out[(long)b * DIM + k] = prelu_f(s + bs0[k], A0);
        }
    }
}

extern "C" void kernel_launch(void* const* d_in, const int* in_sizes, int n_in,
                              void* d_out, int out_size)
{
    const float* points = (const float*)d_in[0];
    const float* vec2   = (const float*)d_in[1];
    const float* vec1   = (const float*)d_in[2];
    const float* vec0   = (const float*)d_in[3];
    const float* Wp     = (const float*)d_in[4];
    const float* bp     = (const float*)d_in[5];
    const float* a_leaf = (const float*)d_in[6];
    const float* Wb2    = (const float*)d_in[7];
    const float* bb2    = (const float*)d_in[8];
    const float* a2     = (const float*)d_in[9];
    const float* Wb1    = (const float*)d_in[10];
    const float* bb1    = (const float*)d_in[11];
    const float* Ws1    = (const float*)d_in[12];
    const float* bs1    = (const float*)d_in[13];
    const float* a1     = (const float*)d_in[14];
    const float* Wb0    = (const float*)d_in[15];
    const float* bb0    = (const float*)d_in[16];
    const float* Ws0    = (const float*)d_in[17];
    const float* bs0    = (const float*)d_in[18];
    const float* a0     = (const float*)d_in[19];
    const int*   cl2    = (const int*)d_in[20];
    const int*   cr2    = (const int*)d_in[21];
    const int*   cl1    = (const int*)d_in[22];
    const int*   cr1    = (const int*)d_in[23];
    const int*   cs1    = (const int*)d_in[24];
    const int*   cl0    = (const int*)d_in[25];
    const int*   cr0    = (const int*)d_in[26];
    const int*   cs0    = (const int*)d_in[27];

    const int B  = out_size / DIM;          // 8
    const int N3 = in_sizes[0] / (3 * B);   // 131072
    const int N2 = in_sizes[1] / (3 * B);   // 65536
    const int N1 = in_sizes[2] / (3 * B);   // 1024

    encoder_cone_kernel<<<B, NTHREADS>>>(
        points, vec2, vec1, vec0,
        Wp, bp, a_leaf, Wb2, bb2, a2,
        Wb1, bb1, Ws1, bs1, a1,
        Wb0, bb0, Ws0, bs0, a0,
        cl2, cr2, cl1, cr1, cs1, cl0, cr0, cs0,
        (float*)d_out, N3, N2, N1);
}

// round 3
// speedup vs baseline: 8.8980x; 1.2385x over previous
#include <cuda_runtime.h>

#define DIM 128
#define D2  256

// ---------------- global scratch (static __device__, no allocation) ----------------
__device__ float g_z2[8][5][768];
__device__ float g_leaf2[8][2][DIM];   // leaf rows for cs1[l1a], cs1[l1b]
__device__ float g_h2[8][5][DIM];
__device__ float g_sink;

__device__ __forceinline__ float prelu_f(float x, float a) {
    return x >= 0.0f ? x : a * x;
}

__device__ __forceinline__ float wred(float v) {
    v += __shfl_xor_sync(0xffffffffu, v, 16);
    v += __shfl_xor_sync(0xffffffffu, v, 8);
    v += __shfl_xor_sync(0xffffffffu, v, 4);
    v += __shfl_xor_sync(0xffffffffu, v, 2);
    v += __shfl_xor_sync(0xffffffffu, v, 1);
    return v;
}

__device__ __forceinline__ float dot4(float4 a, float4 b) {
    return fmaf(a.x, b.x, fmaf(a.y, b.y, fmaf(a.z, b.z, a.w * b.w)));
}

// ================= K1: indices + leaves + z2 build, plus L2 weight prefetch =================
#define K1_WORK 8
#define K1_PF   40
__global__ __launch_bounds__(256) void k1_kernel(
    const float* __restrict__ points,  // [B, N3, 3]
    const float* __restrict__ vec2,    // [B, N2, 3]
    const float* __restrict__ Wp,      // [DIM, 3]
    const float* __restrict__ bp,
    const float* __restrict__ a_leaf,
    const int* __restrict__ cl2, const int* __restrict__ cr2,
    const int* __restrict__ cl1, const int* __restrict__ cr1,
    const int* __restrict__ cs1,
    const int* __restrict__ cl0, const int* __restrict__ cr0,
    const int* __restrict__ cs0,
    const float* __restrict__ Wb2, const float* __restrict__ Wb1,
    const float* __restrict__ Ws1, const float* __restrict__ Wb0,
    const float* __restrict__ Ws0,
    int N3, int N2n)
{
    const int tid = threadIdx.x;

    if (blockIdx.x >= K1_WORK) {
        // ---- prefetch blocks: pull all downstream weights into L2 ----
        const int gtid = (blockIdx.x - K1_WORK) * 256 + tid;
        const int nth  = K1_PF * 256;
        float acc = 0.f;
        const float4* w;
        w = (const float4*)Wb2; for (int i = gtid; i < 24576; i += nth) acc += w[i].x;
        w = (const float4*)Wb1; for (int i = gtid; i < 24576; i += nth) acc += w[i].x;
        w = (const float4*)Ws1; for (int i = gtid; i < 8192;  i += nth) acc += w[i].x;
        w = (const float4*)Wb0; for (int i = gtid; i < 24576; i += nth) acc += w[i].x;
        w = (const float4*)Ws0; for (int i = gtid; i < 8192;  i += nth) acc += w[i].x;
        if (acc == 1.2345e30f) g_sink = acc;   // never true; keeps loads live
        return;
    }

    // ---- work blocks: one per batch ----
    const int b = blockIdx.x;
    __shared__ int sp[12];
    __shared__ int sn2[5];
    __shared__ float leaf[12][DIM];

    if (tid == 0) {
        int l1a = cl0[0];
        int l1b = cr0[0];
        int n0 = cl1[l1a], n1 = cr1[l1a], n2_ = cl1[l1b], n3 = cr1[l1b], n4 = cs0[0];
        sn2[0] = n0; sn2[1] = n1; sn2[2] = n2_; sn2[3] = n3; sn2[4] = n4;
        sp[0] = cl2[n0];  sp[1] = cr2[n0];
        sp[2] = cl2[n1];  sp[3] = cr2[n1];
        sp[4] = cl2[n2_]; sp[5] = cr2[n2_];
        sp[6] = cl2[n3];  sp[7] = cr2[n3];
        sp[8] = cl2[n4];  sp[9] = cr2[n4];
        sp[10] = cs1[l1a]; sp[11] = cs1[l1b];
    }
    __syncthreads();

    const float AL = a_leaf[0];

    // 12 leaf rows: h3 = prelu(points @ Wp^T + bp)
    for (int i = tid; i < 12 * DIM; i += 256) {
        int j = i >> 7, k = i & 127;
        const float* pt = points + ((long)b * N3 + sp[j]) * 3;
        float h = fmaf(Wp[k * 3 + 0], pt[0],
                  fmaf(Wp[k * 3 + 1], pt[1],
                  fmaf(Wp[k * 3 + 2], pt[2], bp[k])));
        leaf[j][k] = prelu_f(h, AL);
    }
    __syncthreads();

    // persist leaf rows 10,11 (needed for layer-1 sample merge)
    if (tid < 2 * DIM)
        g_leaf2[b][tid >> 7][tid & 127] = leaf[10 + (tid >> 7)][tid & 127];

    // z2[j][e] = xcat_j[e/3] * vec2[b, n2[j], e%3]
    for (int i = tid; i < 5 * 768; i += 256) {
        int j = i / 768;
        int e = i - j * 768;
        unsigned d = (unsigned)e / 3u;
        int v = e - 3 * (int)d;
        float x = leaf[2 * j + (d >> 7)][d & 127];
        g_z2[b][j][e] = x * vec2[((long)b * N2n + sn2[j]) * 3 + v];
    }
}

// ================= K2: layer-2 bilinear, 128 blocks (batch x k-chunk) =================
__global__ __launch_bounds__(256) void k2_kernel(
    const float* __restrict__ Wb2,   // [DIM, 768]
    const float* __restrict__ bb2,
    const float* __restrict__ a2p)
{
    const int b  = blockIdx.x >> 4;
    const int kc = (blockIdx.x & 15) << 3;
    const int tid = threadIdx.x;
    const int w = tid >> 5, l = tid & 31;

    __shared__ __align__(16) float4 zs[5 * 192];
    const float4* zg = (const float4*)g_z2[b];
    for (int i = tid; i < 5 * 192; i += 256) zs[i] = zg[i];
    __syncthreads();

    const int k = kc + w;
    const float4* Wr = (const float4*)Wb2 + (long)k * 192;
    float acc[5] = {0.f, 0.f, 0.f, 0.f, 0.f};
    #pragma unroll
    for (int t = 0; t < 6; t++) {
        float4 wv = Wr[t * 32 + l];
        #pragma unroll
        for (int j = 0; j < 5; j++)
            acc[j] += dot4(wv, zs[j * 192 + t * 32 + l]);
    }
    const float A2 = a2p[0];
    const float bk = bb2[k];
    #pragma unroll
    for (int j = 0; j < 5; j++) {
        float s = wred(acc[j]);
        if (l == 0) g_h2[b][j][k] = prelu_f(s + bk, A2);
    }
}

// ================= K3: layer-1 + root tail, grid 8 x 1024 =================
__global__ __launch_bounds__(1024) void k3_kernel(
    const float* __restrict__ vec1,    // [B, N1, 3]
    const float* __restrict__ vec0,    // [B, 1, 3]
    const float* __restrict__ Wb1, const float* __restrict__ bb1,
    const float* __restrict__ Ws1, const float* __restrict__ bs1,
    const float* __restrict__ a1p,
    const float* __restrict__ Wb0, const float* __restrict__ bb0,
    const float* __restrict__ Ws0, const float* __restrict__ bs0,
    const float* __restrict__ a0p,
    const int* __restrict__ cl0, const int* __restrict__ cr0,
    float* __restrict__ out,           // [B, DIM]
    int N1n)
{
    const int b   = blockIdx.x;
    const int tid = threadIdx.x;
    const int w   = tid >> 5, l = tid & 31;

    __shared__ __align__(16) float h2s[5][DIM];
    __shared__ __align__(16) float lf[2][DIM];
    __shared__ __align__(16) float tb[2][DIM];
    __shared__ __align__(16) float h1s[2][DIM];
    __shared__ __align__(16) float tb0[DIM];
    __shared__ __align__(16) float z1[2][768];
    __shared__ __align__(16) float z0[768];
    __shared__ int sl1[2];

    if (tid == 0) { sl1[0] = cl0[0]; sl1[1] = cr0[0]; }
    for (int i = tid; i < 5 * DIM; i += 1024) h2s[i >> 7][i & 127] = g_h2[b][i >> 7][i & 127];
    if (tid < 2 * DIM) lf[tid >> 7][tid & 127] = g_leaf2[b][tid >> 7][tid & 127];
    __syncthreads();

    const float A1 = a1p[0], A0 = a0p[0];

    // z1[j][e] = h2cat_j[e/3] * vec1[b, sl1[j], e%3]
    for (int i = tid; i < 2 * 768; i += 1024) {
        int j = i >= 768 ? 1 : 0;
        int e = i - j * 768;
        unsigned d = (unsigned)e / 3u;
        int v = e - 3 * (int)d;
        float x = h2s[2 * j + (d >> 7)][d & 127];
        z1[j][e] = x * vec1[((long)b * N1n + sl1[j]) * 3 + v];
    }
    __syncthreads();

    // Layer-1 bilinear: 256 warp-dots of length 768
    #pragma unroll
    for (int jj = 0; jj < 8; jj++) {
        int idx = (w << 3) + jj;
        int j = idx >> 7, k = idx & 127;
        const float4* Wr = (const float4*)Wb1 + (long)k * 192;
        const float4* zr = (const float4*)z1[j];
        float acc = 0.f;
        #pragma unroll
        for (int t = 0; t < 6; t++)
            acc += dot4(Wr[t * 32 + l], zr[t * 32 + l]);
        float s = wred(acc);
        if (l == 0) tb[j][k] = prelu_f(s + bb1[k], A1);
    }
    __syncthreads();

    // Layer-1 sample-merge linear: x = concat(tb[j], lf[j])
    #pragma unroll
    for (int jj = 0; jj < 8; jj++) {
        int idx = (w << 3) + jj;
        int j = idx >> 7, k = idx & 127;
        const float4* Wr = (const float4*)Ws1 + (long)k * 64;
        float acc = dot4(Wr[l],      ((const float4*)tb[j])[l]);
        acc      += dot4(Wr[32 + l], ((const float4*)lf[j])[l]);
        float s = wred(acc);
        if (l == 0) h1s[j][k] = prelu_f(s + bs1[k], A1);
    }
    __syncthreads();

    // z0[e] = h1cat[e/3] * vec0[b, e%3]
    if (tid < 768) {
        int e = tid;
        unsigned d = (unsigned)e / 3u;
        int v = e - 3 * (int)d;
        z0[e] = h1s[d >> 7][d & 127] * vec0[(long)b * 3 + v];
    }
    __syncthreads();

    // Root bilinear: 128 warp-dots of length 768
    #pragma unroll
    for (int kk = 0; kk < 4; kk++) {
        int k = (w << 2) + kk;
        const float4* Wr = (const float4*)Wb0 + (long)k * 192;
        float acc = 0.f;
        #pragma unroll
        for (int t = 0; t < 6; t++)
            acc += dot4(Wr[t * 32 + l], ((const float4*)z0)[t * 32 + l]);
        float s = wred(acc);
        if (l == 0) tb0[k] = prelu_f(s + bb0[k], A0);
    }
    __syncthreads();

    // Root linear: x = concat(tb0, h2s[4])
    #pragma unroll
    for (int kk = 0; kk < 4; kk++) {
        int k = (w << 2) + kk;
        const float4* Wr = (const float4*)Ws0 + (long)k * 64;
        float acc = dot4(Wr[l],      ((const float4*)tb0)[l]);
        acc      += dot4(Wr[32 + l], ((const float4*)h2s[4])[l]);
        float s = wred(acc);
        if (l == 0) out[(long)b * DIM + k] = prelu_f(s + bs0[k], A0);
    }
}

// ================= launch =================
extern "C" void kernel_launch(void* const* d_in, const int* in_sizes, int n_in,
                              void* d_out, int out_size)
{
    const float* points = (const float*)d_in[0];
    const float* vec2   = (const float*)d_in[1];
    const float* vec1   = (const float*)d_in[2];
    const float* vec0   = (const float*)d_in[3];
    const float* Wp     = (const float*)d_in[4];
    const float* bp     = (const float*)d_in[5];
    const float* a_leaf = (const float*)d_in[6];
    const float* Wb2    = (const float*)d_in[7];
    const float* bb2    = (const float*)d_in[8];
    const float* a2     = (const float*)d_in[9];
    const float* Wb1    = (const float*)d_in[10];
    const float* bb1    = (const float*)d_in[11];
    const float* Ws1    = (const float*)d_in[12];
    const float* bs1    = (const float*)d_in[13];
    const float* a1     = (const float*)d_in[14];
    const float* Wb0    = (const float*)d_in[15];
    const float* bb0    = (const float*)d_in[16];
    const float* Ws0    = (const float*)d_in[17];
    const float* bs0    = (const float*)d_in[18];
    const float* a0     = (const float*)d_in[19];
    const int*   cl2    = (const int*)d_in[20];
    const int*   cr2    = (const int*)d_in[21];
    const int*   cl1    = (const int*)d_in[22];
    const int*   cr1    = (const int*)d_in[23];
    const int*   cs1    = (const int*)d_in[24];
    const int*   cl0    = (const int*)d_in[25];
    const int*   cr0    = (const int*)d_in[26];
    const int*   cs0    = (const int*)d_in[27];

    const int B  = out_size / DIM;          // 8
    const int N3 = in_sizes[0] / (3 * B);   // 131072
    const int N2 = in_sizes[1] / (3 * B);   // 65536
    const int N1 = in_sizes[2] / (3 * B);   // 1024

    k1_kernel<<<K1_WORK + K1_PF, 256>>>(
        points, vec2, Wp, bp, a_leaf,
        cl2, cr2, cl1, cr1, cs1, cl0, cr0, cs0,
        Wb2, Wb1, Ws1, Wb0, Ws0, N3, N2);

    k2_kernel<<<128, 256>>>(Wb2, bb2, a2);

    k3_kernel<<<B, 1024>>>(
        vec1, vec0,
        Wb1, bb1, Ws1, bs1, a1,
        Wb0, bb0, Ws0, bs0, a0,
        cl0, cr0, (float*)d_out, N1);
}

// round 5
// speedup vs baseline: 10.5529x; 1.1860x over previous
#include <cuda_runtime.h>

#define DIM 128
#define NSLICE 16          // k-slices per batch
#define NTHREADS 256       // 8 warps per block

// ---------------- global scratch (static __device__, no allocation) ----------------
__device__ float g_h2[8][5][DIM];
__device__ float g_tb[8][2][DIM];
__device__ float g_h1[8][2][DIM];
__device__ float g_tb0[8][DIM];

// grid barrier state (monotonic generation; replay-safe; zero-init at load)
__device__ unsigned g_bar_count[4];
__device__ unsigned g_bar_gen[4];

__device__ __forceinline__ void grid_bar(int slot, unsigned nb) {
    __syncthreads();
    if (threadIdx.x == 0) {
        volatile unsigned* genp = (volatile unsigned*)&g_bar_gen[slot];
        unsigned my = *genp;
        __threadfence();
        unsigned old = atomicAdd(&g_bar_count[slot], 1u);
        if (old == nb - 1u) {
            g_bar_count[slot] = 0u;
            __threadfence();
            atomicAdd((unsigned*)&g_bar_gen[slot], 1u);
        } else {
            while (*genp == my) { }
        }
        __threadfence();
    }
    __syncthreads();
}

__device__ __forceinline__ float prelu_f(float x, float a) {
    return x >= 0.0f ? x : a * x;
}

// xor-butterfly: leaves the FULL sum in EVERY lane (uniform warp execution)
__device__ __forceinline__ float wred(float v) {
    v += __shfl_xor_sync(0xffffffffu, v, 16);
    v += __shfl_xor_sync(0xffffffffu, v, 8);
    v += __shfl_xor_sync(0xffffffffu, v, 4);
    v += __shfl_xor_sync(0xffffffffu, v, 2);
    v += __shfl_xor_sync(0xffffffffu, v, 1);
    return v;
}

__device__ __forceinline__ float dot4(float4 a, float4 b) {
    return fmaf(a.x, b.x, fmaf(a.y, b.y, fmaf(a.z, b.z, a.w * b.w)));
}

__global__ __launch_bounds__(NTHREADS) void encoder_fused_kernel(
    const float* __restrict__ points,  // [B, N3, 3]
    const float* __restrict__ vec2,    // [B, N2, 3]
    const float* __restrict__ vec1,    // [B, N1, 3]
    const float* __restrict__ vec0,    // [B, 1, 3]
    const float* __restrict__ Wp,      // [DIM, 3]
    const float* __restrict__ bp,
    const float* __restrict__ a_leaf,
    const float* __restrict__ Wb2, const float* __restrict__ bb2,
    const float* __restrict__ a2p,
    const float* __restrict__ Wb1, const float* __restrict__ bb1,
    const float* __restrict__ Ws1, const float* __restrict__ bs1,
    const float* __restrict__ a1p,
    const float* __restrict__ Wb0, const float* __restrict__ bb0,
    const float* __restrict__ Ws0, const float* __restrict__ bs0,
    const float* __restrict__ a0p,
    const int* __restrict__ cl2, const int* __restrict__ cr2,
    const int* __restrict__ cl1, const int* __restrict__ cr1,
    const int* __restrict__ cs1,
    const int* __restrict__ cl0, const int* __restrict__ cr0,
    const int* __restrict__ cs0,
    float* __restrict__ out,           // [B, DIM]
    int N3, int N2n, int N1n)
{
    const int b   = blockIdx.x >> 4;        // batch
    const int s   = blockIdx.x & (NSLICE-1);// k-slice
    const unsigned nb = gridDim.x;
    const int tid = threadIdx.x;
    const int w   = tid >> 5, l = tid & 31;

    __shared__ int sp[12], sn2[5], sl1[2];
    __shared__ __align__(16) float leaf[12][DIM];   // persistent
    __shared__ __align__(16) float zbuf[5 * 768];   // z2 -> z1 -> z0 (reused)
    __shared__ __align__(16) float h2all[5][DIM];
    __shared__ __align__(16) float tbs[2][DIM];
    __shared__ __align__(16) float h1all[2][DIM];
    __shared__ __align__(16) float tb0s[DIM];

    // ---- resolve the (batch-invariant) dependency cone, per block ----
    if (tid == 0) {
        int l1a = cl0[0];
        int l1b = cr0[0];
        sl1[0] = l1a; sl1[1] = l1b;
        int n0 = cl1[l1a], n1 = cr1[l1a], n2_ = cl1[l1b], n3 = cr1[l1b], n4 = cs0[0];
        sn2[0] = n0; sn2[1] = n1; sn2[2] = n2_; sn2[3] = n3; sn2[4] = n4;
        sp[0] = cl2[n0];  sp[1] = cr2[n0];
        sp[2] = cl2[n1];  sp[3] = cr2[n1];
        sp[4] = cl2[n2_]; sp[5] = cr2[n2_];
        sp[6] = cl2[n3];  sp[7] = cr2[n3];
        sp[8] = cl2[n4];  sp[9] = cr2[n4];
        sp[10] = cs1[l1a]; sp[11] = cs1[l1b];
    }
    __syncthreads();

    const float AL = a_leaf[0], A2 = a2p[0], A1 = a1p[0], A0 = a0p[0];

    // ---- leaves: 12 rows, h3 = prelu(points @ Wp^T + bp) ----
    for (int i = tid; i < 12 * DIM; i += NTHREADS) {
        int j = i >> 7, k = i & 127;
        const float* pt = points + ((long)b * N3 + sp[j]) * 3;
        float h = fmaf(Wp[k * 3 + 0], pt[0],
                  fmaf(Wp[k * 3 + 1], pt[1],
                  fmaf(Wp[k * 3 + 2], pt[2], bp[k])));
        leaf[j][k] = prelu_f(h, AL);
    }
    __syncthreads();

    // ---- z2[j][e] = xcat_j[e/3] * vec2[b, n2[j], e%3] (full, per block) ----
    for (int i = tid; i < 5 * 768; i += NTHREADS) {
        int j = i / 768;
        int e = i - j * 768;
        unsigned d = (unsigned)e / 3u;
        int v = e - 3 * (int)d;
        float x = leaf[2 * j + (d >> 7)][d & 127];
        zbuf[i] = x * vec2[((long)b * N2n + sn2[j]) * 3 + v];
    }
    __syncthreads();

    // ---- Phase B: layer-2 bilinear; warp w handles k = s*8 + w, 5 nodes ----
    {
        const int k = (s << 3) + w;
        const float4* Wr = (const float4*)Wb2 + (long)k * 192;
        const float4* zr = (const float4*)zbuf;
        float acc[5] = {0.f, 0.f, 0.f, 0.f, 0.f};
        #pragma unroll
        for (int t = 0; t < 6; t++) {
            float4 wv = Wr[t * 32 + l];
            #pragma unroll
            for (int j = 0; j < 5; j++)
                acc[j] += dot4(wv, zr[j * 192 + t * 32 + l]);
        }
        const float bk = bb2[k];
        #pragma unroll
        for (int j = 0; j < 5; j++) {
            float r = wred(acc[j]);
            if (l == 0) g_h2[b][j][k] = prelu_f(r + bk, A2);
        }
    }
    grid_bar(0, nb);

    // ---- load h2, build z1 (reuse zbuf) ----
    for (int i = tid; i < 5 * DIM; i += NTHREADS)
        h2all[i >> 7][i & 127] = g_h2[b][i >> 7][i & 127];
    __syncthreads();
    for (int i = tid; i < 2 * 768; i += NTHREADS) {
        int j = i >= 768 ? 1 : 0;
        int e = i - j * 768;
        unsigned d = (unsigned)e / 3u;
        int v = e - 3 * (int)d;
        float x = h2all[2 * j + (d >> 7)][d & 127];
        zbuf[i] = x * vec1[((long)b * N1n + sl1[j]) * 3 + v];
    }
    __syncthreads();

    // ---- Phase C: layer-1 bilinear; warp w -> idx pair (s*16+2w, +1) ----
    {
        const int idx = (s << 4) + (w << 1);
        const int j = idx >> 7;
        const int k0 = idx & 127, k1 = k0 + 1;
        const float4* W0 = (const float4*)Wb1 + (long)k0 * 192;
        const float4* W1 = (const float4*)Wb1 + (long)k1 * 192;
        const float4* zr = (const float4*)(zbuf + j * 768);
        float a0 = 0.f, a1 = 0.f;
        #pragma unroll
        for (int t = 0; t < 6; t++) {
            float4 zz = zr[t * 32 + l];
            a0 += dot4(W0[t * 32 + l], zz);
            a1 += dot4(W1[t * 32 + l], zz);
        }
        float r0 = wred(a0), r1 = wred(a1);   // full sums valid in every lane
        if (l == 0)      g_tb[b][j][k0] = prelu_f(r0 + bb1[k0], A1);
        else if (l == 1) g_tb[b][j][k1] = prelu_f(r1 + bb1[k1], A1);
    }
    grid_bar(1, nb);

    // ---- load tb ----
    for (int i = tid; i < 2 * DIM; i += NTHREADS)
        tbs[i >> 7][i & 127] = g_tb[b][i >> 7][i & 127];
    __syncthreads();

    // ---- Phase D: layer-1 sample-merge linear; x = concat(tbs[j], leaf[10+j]) ----
    {
        const int idx = (s << 4) + (w << 1);
        const int j = idx >> 7;
        const int k0 = idx & 127, k1 = k0 + 1;
        const float4* W0 = (const float4*)Ws1 + (long)k0 * 64;
        const float4* W1 = (const float4*)Ws1 + (long)k1 * 64;
        float4 xa = ((const float4*)tbs[j])[l];
        float4 xb = ((const float4*)leaf[10 + j])[l];
        float a0 = dot4(W0[l], xa) + dot4(W0[32 + l], xb);
        float a1 = dot4(W1[l], xa) + dot4(W1[32 + l], xb);
        float r0 = wred(a0), r1 = wred(a1);
        if (l == 0)      g_h1[b][j][k0] = prelu_f(r0 + bs1[k0], A1);
        else if (l == 1) g_h1[b][j][k1] = prelu_f(r1 + bs1[k1], A1);
    }
    grid_bar(2, nb);

    // ---- load h1, build z0 (reuse zbuf) ----
    for (int i = tid; i < 2 * DIM; i += NTHREADS)
        h1all[i >> 7][i & 127] = g_h1[b][i >> 7][i & 127];
    __syncthreads();
    for (int e = tid; e < 768; e += NTHREADS) {
        unsigned d = (unsigned)e / 3u;
        int v = e - 3 * (int)d;
        zbuf[e] = h1all[d >> 7][d & 127] * vec0[(long)b * 3 + v];
    }
    __syncthreads();

    // ---- Phase E: root bilinear; warp w -> k = s*8 + w ----
    {
        const int k = (s << 3) + w;
        const float4* Wr = (const float4*)Wb0 + (long)k * 192;
        const float4* zr = (const float4*)zbuf;
        float acc = 0.f;
        #pragma unroll
        for (int t = 0; t < 6; t++)
            acc += dot4(Wr[t * 32 + l], zr[t * 32 + l]);
        float r = wred(acc);
        if (l == 0) g_tb0[b][k] = prelu_f(r + bb0[k], A0);
    }
    grid_bar(3, nb);

    // ---- load tb0; Phase F: root linear; x = concat(tb0, h2all[4]) ----
    if (tid < DIM) tb0s[tid] = g_tb0[b][tid];
    __syncthreads();
    {
        const int k = (s << 3) + w;
        const float4* Wr = (const float4*)Ws0 + (long)k * 64;
        float acc = dot4(Wr[l],      ((const float4*)tb0s)[l]);
        acc      += dot4(Wr[32 + l], ((const float4*)h2all[4])[l]);
        float r = wred(acc);
        if (l == 0) out[(long)b * DIM + k] = prelu_f(r + bs0[k], A0);
    }
}

extern "C" void kernel_launch(void* const* d_in, const int* in_sizes, int n_in,
                              void* d_out, int out_size)
{
    const float* points = (const float*)d_in[0];
    const float* vec2   = (const float*)d_in[1];
    const float* vec1   = (const float*)d_in[2];
    const float* vec0   = (const float*)d_in[3];
    const float* Wp     = (const float*)d_in[4];
    const float* bp     = (const float*)d_in[5];
    const float* a_leaf = (const float*)d_in[6];
    const float* Wb2    = (const float*)d_in[7];
    const float* bb2    = (const float*)d_in[8];
    const float* a2     = (const float*)d_in[9];
    const float* Wb1    = (const float*)d_in[10];
    const float* bb1    = (const float*)d_in[11];
    const float* Ws1    = (const float*)d_in[12];
    const float* bs1    = (const float*)d_in[13];
    const float* a1     = (const float*)d_in[14];
    const float* Wb0    = (const float*)d_in[15];
    const float* bb0    = (const float*)d_in[16];
    const float* Ws0    = (const float*)d_in[17];
    const float* bs0    = (const float*)d_in[18];
    const float* a0     = (const float*)d_in[19];
    const int*   cl2    = (const int*)d_in[20];
    const int*   cr2    = (const int*)d_in[21];
    const int*   cl1    = (const int*)d_in[22];
    const int*   cr1    = (const int*)d_in[23];
    const int*   cs1    = (const int*)d_in[24];
    const int*   cl0    = (const int*)d_in[25];
    const int*   cr0    = (const int*)d_in[26];
    const int*   cs0    = (const int*)d_in[27];

    const int B  = out_size / DIM;          // 8
    const int N3 = in_sizes[0] / (3 * B);   // 131072
    const int N2 = in_sizes[1] / (3 * B);   // 65536
    const int N1 = in_sizes[2] / (3 * B);   // 1024

    encoder_fused_kernel<<<B * NSLICE, NTHREADS>>>(
        points, vec2, vec1, vec0,
        Wp, bp, a_leaf, Wb2, bb2, a2,
        Wb1, bb1, Ws1, bs1, a1,
        Wb0, bb0, Ws0, bs0, a0,
        cl2, cr2, cl1, cr1, cs1, cl0, cr0, cs0,
        (float*)d_out, N3, N2, N1);
}

// round 6
// speedup vs baseline: 11.8852x; 1.1263x over previous
#include <cuda_runtime.h>

#define DIM 128
#define NSLICE 16          // k-slices per batch
#define NTHREADS 256       // 8 warps per block
#define NBATCH 8

// ---------------- global scratch (static __device__, no allocation) ----------------
__device__ float g_h2[NBATCH][5][DIM];
__device__ float g_tb[NBATCH][2][DIM];
__device__ float g_h1[NBATCH][2][DIM];
__device__ float g_tb0[NBATCH][DIM];

// per-batch barrier state: slot = batch*4 + phase (monotonic generation, replay-safe)
__device__ unsigned g_bar_count[NBATCH * 4];
__device__ unsigned g_bar_gen[NBATCH * 4];

__device__ __forceinline__ void batch_bar(int slot) {
    __syncthreads();
    if (threadIdx.x == 0) {
        volatile unsigned* genp = (volatile unsigned*)&g_bar_gen[slot];
        unsigned my = *genp;
        __threadfence();                       // release: phase stores visible
        unsigned old = atomicAdd(&g_bar_count[slot], 1u);
        if (old == NSLICE - 1u) {
            g_bar_count[slot] = 0u;
            __threadfence();
            atomicAdd((unsigned*)&g_bar_gen[slot], 1u);
        } else {
            while (*genp == my) { }
        }
        __threadfence();                       // acquire: peer stores visible
    }
    __syncthreads();
}

__device__ __forceinline__ float prelu_f(float x, float a) {
    return x >= 0.0f ? x : a * x;
}

// xor-butterfly: full sum in EVERY lane
__device__ __forceinline__ float wred(float v) {
    v += __shfl_xor_sync(0xffffffffu, v, 16);
    v += __shfl_xor_sync(0xffffffffu, v, 8);
    v += __shfl_xor_sync(0xffffffffu, v, 4);
    v += __shfl_xor_sync(0xffffffffu, v, 2);
    v += __shfl_xor_sync(0xffffffffu, v, 1);
    return v;
}

__device__ __forceinline__ float dot4(float4 a, float4 b) {
    return fmaf(a.x, b.x, fmaf(a.y, b.y, fmaf(a.z, b.z, a.w * b.w)));
}

__global__ __launch_bounds__(NTHREADS, 1) void encoder_fused_kernel(
    const float* __restrict__ points,  // [B, N3, 3]
    const float* __restrict__ vec2,    // [B, N2, 3]
    const float* __restrict__ vec1,    // [B, N1, 3]
    const float* __restrict__ vec0,    // [B, 1, 3]
    const float* __restrict__ Wp,      // [DIM, 3]
    const float* __restrict__ bp,
    const float* __restrict__ a_leaf,
    const float* __restrict__ Wb2, const float* __restrict__ bb2,
    const float* __restrict__ a2p,
    const float* __restrict__ Wb1, const float* __restrict__ bb1,
    const float* __restrict__ Ws1, const float* __restrict__ bs1,
    const float* __restrict__ a1p,
    const float* __restrict__ Wb0, const float* __restrict__ bb0,
    const float* __restrict__ Ws0, const float* __restrict__ bs0,
    const float* __restrict__ a0p,
    const int* __restrict__ cl2, const int* __restrict__ cr2,
    const int* __restrict__ cl1, const int* __restrict__ cr1,
    const int* __restrict__ cs1,
    const int* __restrict__ cl0, const int* __restrict__ cr0,
    const int* __restrict__ cs0,
    float* __restrict__ out,           // [B, DIM]
    int N3, int N2n, int N1n)
{
    const int b   = blockIdx.x >> 4;
    const int s   = blockIdx.x & (NSLICE - 1);
    const int tid = threadIdx.x;
    const int w   = tid >> 5, l = tid & 31;

    // ---------------- register-preload ALL weight slices (no dependencies) ----------------
    const int kB  = (s << 3) + w;           // phase B/E/F channel
    const int idx = (s << 4) + (w << 1);    // phase C/D pair base
    const int jCD = idx >> 7;
    const int k0  = idx & 127, k1 = k0 + 1;

    float4 wB[6], wC0[6], wC1[6], wE[6];
    float4 wD0[2], wD1[2], wF[2];
    {
        const float4* p1 = (const float4*)Wb2 + (long)kB * 192;
        const float4* p2 = (const float4*)Wb1 + (long)k0 * 192;
        const float4* p3 = (const float4*)Wb1 + (long)k1 * 192;
        const float4* p4 = (const float4*)Wb0 + (long)kB * 192;
        #pragma unroll
        for (int t = 0; t < 6; t++) {
            wB[t]  = p1[t * 32 + l];
            wC0[t] = p2[t * 32 + l];
            wC1[t] = p3[t * 32 + l];
            wE[t]  = p4[t * 32 + l];
        }
        const float4* p5 = (const float4*)Ws1 + (long)k0 * 64;
        const float4* p6 = (const float4*)Ws1 + (long)k1 * 64;
        const float4* p7 = (const float4*)Ws0 + (long)kB * 64;
        wD0[0] = p5[l]; wD0[1] = p5[32 + l];
        wD1[0] = p6[l]; wD1[1] = p6[32 + l];
        wF[0]  = p7[l]; wF[1]  = p7[32 + l];
    }
    const float bB  = bb2[kB];
    const float bC0 = bb1[k0], bC1 = bb1[k1];
    const float bD0 = bs1[k0], bD1 = bs1[k1];
    const float bE  = bb0[kB], bF = bs0[kB];
    const float AL = a_leaf[0], A2 = a2p[0], A1 = a1p[0], A0 = a0p[0];

    __shared__ int sp[12], sn2[5], sl1[2];
    __shared__ __align__(16) float svec2[5][3];
    __shared__ __align__(16) float svec1[2][3];
    __shared__ __align__(16) float svec0[3];
    __shared__ __align__(16) float leaf[12][DIM];
    __shared__ __align__(16) float zbuf[5 * 768];   // z2 -> z1 -> z0 (reused)
    __shared__ __align__(16) float h2all[5][DIM];
    __shared__ __align__(16) float tbs[2][DIM];
    __shared__ __align__(16) float h1all[2][DIM];
    __shared__ __align__(16) float tb0s[DIM];

    // ---- resolve the (batch-invariant) dependency cone ----
    if (tid == 0) {
        int l1a = cl0[0];
        int l1b = cr0[0];
        sl1[0] = l1a; sl1[1] = l1b;
        int n0 = cl1[l1a], n1 = cr1[l1a], n2_ = cl1[l1b], n3 = cr1[l1b], n4 = cs0[0];
        sn2[0] = n0; sn2[1] = n1; sn2[2] = n2_; sn2[3] = n3; sn2[4] = n4;
        sp[0] = cl2[n0];  sp[1] = cr2[n0];
        sp[2] = cl2[n1];  sp[3] = cr2[n1];
        sp[4] = cl2[n2_]; sp[5] = cr2[n2_];
        sp[6] = cl2[n3];  sp[7] = cr2[n3];
        sp[8] = cl2[n4];  sp[9] = cr2[n4];
        sp[10] = cs1[l1a]; sp[11] = cs1[l1b];
    }
    __syncthreads();

    // ---- preload vec gathers into smem (no barrier dependencies) ----
    if (tid < 15) {
        int j = tid / 3, v = tid - 3 * j;
        svec2[j][v] = vec2[((long)b * N2n + sn2[j]) * 3 + v];
    } else if (tid < 21) {
        int t = tid - 15;
        int j = t / 3, v = t - 3 * j;
        svec1[j][v] = vec1[((long)b * N1n + sl1[j]) * 3 + v];
    } else if (tid < 24) {
        svec0[tid - 21] = vec0[(long)b * 3 + (tid - 21)];
    }

    // ---- leaves: 12 rows, h3 = prelu(points @ Wp^T + bp) ----
    for (int i = tid; i < 12 * DIM; i += NTHREADS) {
        int j = i >> 7, k = i & 127;
        const float* pt = points + ((long)b * N3 + sp[j]) * 3;
        float h = fmaf(Wp[k * 3 + 0], pt[0],
                  fmaf(Wp[k * 3 + 1], pt[1],
                  fmaf(Wp[k * 3 + 2], pt[2], bp[k])));
        leaf[j][k] = prelu_f(h, AL);
    }
    __syncthreads();

    // ---- z2 build (smem-only now) ----
    for (int i = tid; i < 5 * 768; i += NTHREADS) {
        int j = i / 768;
        int e = i - j * 768;
        unsigned d = (unsigned)e / 3u;
        int v = e - 3 * (int)d;
        zbuf[i] = leaf[2 * j + (d >> 7)][d & 127] * svec2[j][v];
    }
    __syncthreads();

    // ---- Phase B: layer-2 bilinear, weights in regs ----
    {
        const float4* zr = (const float4*)zbuf;
        float acc[5] = {0.f, 0.f, 0.f, 0.f, 0.f};
        #pragma unroll
        for (int t = 0; t < 6; t++) {
            #pragma unroll
            for (int j = 0; j < 5; j++)
                acc[j] += dot4(wB[t], zr[j * 192 + t * 32 + l]);
        }
        #pragma unroll
        for (int j = 0; j < 5; j++) {
            float r = wred(acc[j]);
            if (l == 0) g_h2[b][j][kB] = prelu_f(r + bB, A2);
        }
    }
    batch_bar(b * 4 + 0);

    // ---- load h2 (one coalesced L2 round), build z1 ----
    for (int i = tid; i < 5 * DIM; i += NTHREADS)
        h2all[i >> 7][i & 127] = g_h2[b][i >> 7][i & 127];
    __syncthreads();
    for (int i = tid; i < 2 * 768; i += NTHREADS) {
        int j = i >= 768 ? 1 : 0;
        int e = i - j * 768;
        unsigned d = (unsigned)e / 3u;
        int v = e - 3 * (int)d;
        zbuf[i] = h2all[2 * j + (d >> 7)][d & 127] * svec1[j][v];
    }
    __syncthreads();

    // ---- Phase C: layer-1 bilinear, weights in regs ----
    {
        const float4* zr = (const float4*)(zbuf + jCD * 768);
        float a0 = 0.f, a1 = 0.f;
        #pragma unroll
        for (int t = 0; t < 6; t++) {
            float4 zz = zr[t * 32 + l];
            a0 += dot4(wC0[t], zz);
            a1 += dot4(wC1[t], zz);
        }
        float r0 = wred(a0), r1 = wred(a1);
        if (l == 0)      g_tb[b][jCD][k0] = prelu_f(r0 + bC0, A1);
        else if (l == 1) g_tb[b][jCD][k1] = prelu_f(r1 + bC1, A1);
    }
    batch_bar(b * 4 + 1);

    // ---- load tb, Phase D: sample-merge linear, weights in regs ----
    for (int i = tid; i < 2 * DIM; i += NTHREADS)
        tbs[i >> 7][i & 127] = g_tb[b][i >> 7][i & 127];
    __syncthreads();
    {
        float4 xa = ((const float4*)tbs[jCD])[l];
        float4 xb = ((const float4*)leaf[10 + jCD])[l];
        float a0 = dot4(wD0[0], xa) + dot4(wD0[1], xb);
        float a1 = dot4(wD1[0], xa) + dot4(wD1[1], xb);
        float r0 = wred(a0), r1 = wred(a1);
        if (l == 0)      g_h1[b][jCD][k0] = prelu_f(r0 + bD0, A1);
        else if (l == 1) g_h1[b][jCD][k1] = prelu_f(r1 + bD1, A1);
    }
    batch_bar(b * 4 + 2);

    // ---- load h1, build z0 ----
    for (int i = tid; i < 2 * DIM; i += NTHREADS)
        h1all[i >> 7][i & 127] = g_h1[b][i >> 7][i & 127];
    __syncthreads();
    for (int e = tid; e < 768; e += NTHREADS) {
        unsigned d = (unsigned)e / 3u;
        int v = e - 3 * (int)d;
        zbuf[e] = h1all[d >> 7][d & 127] * svec0[v];
    }
    __syncthreads();

    // ---- Phase E: root bilinear, weights in regs ----
    {
        const float4* zr = (const float4*)zbuf;
        float acc = 0.f;
        #pragma unroll
        for (int t = 0; t < 6; t++)
            acc += dot4(wE[t], zr[t * 32 + l]);
        float r = wred(acc);
        if (l == 0) g_tb0[b][kB] = prelu_f(r + bE, A0);
    }
    batch_bar(b * 4 + 3);

    // ---- load tb0, Phase F: root linear, weights in regs ----
    if (tid < DIM) tb0s[tid] = g_tb0[b][tid];
    __syncthreads();
    {
        float acc = dot4(wF[0], ((const float4*)tb0s)[l]);
        acc      += dot4(wF[1], ((const float4*)h2all[4])[l]);
        float r = wred(acc);
        if (l == 0) out[(long)b * DIM + kB] = prelu_f(r + bF, A0);
    }
}

extern "C" void kernel_launch(void* const* d_in, const int* in_sizes, int n_in,
                              void* d_out, int out_size)
{
    const float* points = (const float*)d_in[0];
    const float* vec2   = (const float*)d_in[1];
    const float* vec1   = (const float*)d_in[2];
    const float* vec0   = (const float*)d_in[3];
    const float* Wp     = (const float*)d_in[4];
    const float* bp     = (const float*)d_in[5];
    const float* a_leaf = (const float*)d_in[6];
    const float* Wb2    = (const float*)d_in[7];
    const float* bb2    = (const float*)d_in[8];
    const float* a2     = (const float*)d_in[9];
    const float* Wb1    = (const float*)d_in[10];
    const float* bb1    = (const float*)d_in[11];
    const float* Ws1    = (const float*)d_in[12];
    const float* bs1    = (const float*)d_in[13];
    const float* a1     = (const float*)d_in[14];
    const float* Wb0    = (const float*)d_in[15];
    const float* bb0    = (const float*)d_in[16];
    const float* Ws0    = (const float*)d_in[17];
    const float* bs0    = (const float*)d_in[18];
    const float* a0     = (const float*)d_in[19];
    const int*   cl2    = (const int*)d_in[20];
    const int*   cr2    = (const int*)d_in[21];
    const int*   cl1    = (const int*)d_in[22];
    const int*   cr1    = (const int*)d_in[23];
    const int*   cs1    = (const int*)d_in[24];
    const int*   cl0    = (const int*)d_in[25];
    const int*   cr0    = (const int*)d_in[26];
    const int*   cs0    = (const int*)d_in[27];

    const int B  = out_size / DIM;          // 8
    const int N3 = in_sizes[0] / (3 * B);   // 131072
    const int N2 = in_sizes[1] / (3 * B);   // 65536
    const int N1 = in_sizes[2] / (3 * B);   // 1024

    encoder_fused_kernel<<<B * NSLICE, NTHREADS>>>(
        points, vec2, vec1, vec0,
        Wp, bp, a_leaf, Wb2, bb2, a2,
        Wb1, bb1, Ws1, bs1, a1,
        Wb0, bb0, Ws0, bs0, a0,
        cl2, cr2, cl1, cr1, cs1, cl0, cr0, cs0,
        (float*)d_out, N3, N2, N1);
}

// round 7
// speedup vs baseline: 14.3819x; 1.2101x over previous
#include <cuda_runtime.h>

#define DIM 128
#define NSLICE 16          // k-slices per batch
#define NTHREADS 256       // 8 warps per block
#define NBATCH 8

// ---------------- global scratch (static __device__, no allocation) ----------------
__device__ float g_h2[NBATCH][5][DIM];
__device__ float g_tb[NBATCH][2][DIM];
__device__ float g_h1[NBATCH][2][DIM];
__device__ float g_tb0[NBATCH][DIM];

// per-(batch,phase) barrier: ONE monotonic counter, own 128B line (no false sharing)
struct __align__(128) BarSlot { unsigned c; unsigned pad[31]; };
__device__ BarSlot g_bar[NBATCH * 4];

// arrive with release-atomic (old value -> replay-safe target), poll with acquire-load.
// One L2 round-trip total; no MEMBAR, no gen variable, no reset.
__device__ __forceinline__ void batch_bar(int slot) {
    __syncthreads();
    if (threadIdx.x == 0) {
        unsigned* cp = &g_bar[slot].c;
        unsigned old;
        asm volatile("atom.release.gpu.global.add.u32 %0, [%1], %2;"
                     : "=r"(old) : "l"(cp), "r"(1u) : "memory");
        unsigned target = (old / NSLICE + 1u) * NSLICE;
        unsigned cur;
        do {
            asm volatile("ld.acquire.gpu.global.u32 %0, [%1];"
                         : "=r"(cur) : "l"(cp) : "memory");
        } while ((int)(cur - target) < 0);   // wrap-safe
    }
    __syncthreads();
}

__device__ __forceinline__ float prelu_f(float x, float a) {
    return x >= 0.0f ? x : a * x;
}

// xor-butterfly: full sum in EVERY lane
__device__ __forceinline__ float wred(float v) {
    v += __shfl_xor_sync(0xffffffffu, v, 16);
    v += __shfl_xor_sync(0xffffffffu, v, 8);
    v += __shfl_xor_sync(0xffffffffu, v, 4);
    v += __shfl_xor_sync(0xffffffffu, v, 2);
    v += __shfl_xor_sync(0xffffffffu, v, 1);
    return v;
}

__device__ __forceinline__ float dot4(float4 a, float4 b) {
    return fmaf(a.x, b.x, fmaf(a.y, b.y, fmaf(a.z, b.z, a.w * b.w)));
}

__global__ __launch_bounds__(NTHREADS, 1) void encoder_fused_kernel(
    const float* __restrict__ points,  // [B, N3, 3]
    const float* __restrict__ vec2,    // [B, N2, 3]
    const float* __restrict__ vec1,    // [B, N1, 3]
    const float* __restrict__ vec0,    // [B, 1, 3]
    const float* __restrict__ Wp,      // [DIM, 3]
    const float* __restrict__ bp,
    const float* __restrict__ a_leaf,
    const float* __restrict__ Wb2, const float* __restrict__ bb2,
    const float* __restrict__ a2p,
    const float* __restrict__ Wb1, const float* __restrict__ bb1,
    const float* __restrict__ Ws1, const float* __restrict__ bs1,
    const float* __restrict__ a1p,
    const float* __restrict__ Wb0, const float* __restrict__ bb0,
    const float* __restrict__ Ws0, const float* __restrict__ bs0,
    const float* __restrict__ a0p,
    const int* __restrict__ cl2, const int* __restrict__ cr2,
    const int* __restrict__ cl1, const int* __restrict__ cr1,
    const int* __restrict__ cs1,
    const int* __restrict__ cl0, const int* __restrict__ cr0,
    const int* __restrict__ cs0,
    float* __restrict__ out,           // [B, DIM]
    int N3, int N2n, int N1n)
{
    const int b   = blockIdx.x >> 4;
    const int s   = blockIdx.x & (NSLICE - 1);
    const int tid = threadIdx.x;
    const int w   = tid >> 5, l = tid & 31;

    // ---------------- register-preload ALL weight slices (no dependencies) ----------------
    const int kB  = (s << 3) + w;           // phase B/E/F channel
    const int idx = (s << 4) + (w << 1);    // phase C/D pair base
    const int jCD = idx >> 7;
    const int k0  = idx & 127, k1 = k0 + 1;

    float4 wB[6], wC0[6], wC1[6], wE[6];
    float4 wD0[2], wD1[2], wF[2];
    {
        const float4* p1 = (const float4*)Wb2 + (long)kB * 192;
        const float4* p2 = (const float4*)Wb1 + (long)k0 * 192;
        const float4* p3 = (const float4*)Wb1 + (long)k1 * 192;
        const float4* p4 = (const float4*)Wb0 + (long)kB * 192;
        #pragma unroll
        for (int t = 0; t < 6; t++) {
            wB[t]  = p1[t * 32 + l];
            wC0[t] = p2[t * 32 + l];
            wC1[t] = p3[t * 32 + l];
            wE[t]  = p4[t * 32 + l];
        }
        const float4* p5 = (const float4*)Ws1 + (long)k0 * 64;
        const float4* p6 = (const float4*)Ws1 + (long)k1 * 64;
        const float4* p7 = (const float4*)Ws0 + (long)kB * 64;
        wD0[0] = p5[l]; wD0[1] = p5[32 + l];
        wD1[0] = p6[l]; wD1[1] = p6[32 + l];
        wF[0]  = p7[l]; wF[1]  = p7[32 + l];
    }
    const float bB  = bb2[kB];
    const float bC0 = bb1[k0], bC1 = bb1[k1];
    const float bD0 = bs1[k0], bD1 = bs1[k1];
    const float bE  = bb0[kB], bF = bs0[kB];
    const float AL = a_leaf[0], A2 = a2p[0], A1 = a1p[0], A0 = a0p[0];

    __shared__ int sp[12], sn2[5], sl1[2];
    __shared__ __align__(16) float svec2[5][3];
    __shared__ __align__(16) float svec1[2][3];
    __shared__ __align__(16) float svec0[3];
    __shared__ __align__(16) float leaf[12][DIM];
    __shared__ __align__(16) float zbuf[5 * 768];   // z2 -> z1 -> z0 (reused)
    __shared__ __align__(16) float h2all[5][DIM];
    __shared__ __align__(16) float tbs[2][DIM];
    __shared__ __align__(16) float h1all[2][DIM];
    __shared__ __align__(16) float tb0s[DIM];

    // ---- resolve the (batch-invariant) dependency cone ----
    if (tid == 0) {
        int l1a = cl0[0];
        int l1b = cr0[0];
        sl1[0] = l1a; sl1[1] = l1b;
        int n0 = cl1[l1a], n1 = cr1[l1a], n2_ = cl1[l1b], n3 = cr1[l1b], n4 = cs0[0];
        sn2[0] = n0; sn2[1] = n1; sn2[2] = n2_; sn2[3] = n3; sn2[4] = n4;
        sp[0] = cl2[n0];  sp[1] = cr2[n0];
        sp[2] = cl2[n1];  sp[3] = cr2[n1];
        sp[4] = cl2[n2_]; sp[5] = cr2[n2_];
        sp[6] = cl2[n3];  sp[7] = cr2[n3];
        sp[8] = cl2[n4];  sp[9] = cr2[n4];
        sp[10] = cs1[l1a]; sp[11] = cs1[l1b];
    }
    __syncthreads();

    // ---- preload vec gathers into smem (no barrier dependencies) ----
    if (tid < 15) {
        int j = tid / 3, v = tid - 3 * j;
        svec2[j][v] = vec2[((long)b * N2n + sn2[j]) * 3 + v];
    } else if (tid < 21) {
        int t = tid - 15;
        int j = t / 3, v = t - 3 * j;
        svec1[j][v] = vec1[((long)b * N1n + sl1[j]) * 3 + v];
    } else if (tid < 24) {
        svec0[tid - 21] = vec0[(long)b * 3 + (tid - 21)];
    }

    // ---- leaves: 12 rows, h3 = prelu(points @ Wp^T + bp) ----
    for (int i = tid; i < 12 * DIM; i += NTHREADS) {
        int j = i >> 7, k = i & 127;
        const float* pt = points + ((long)b * N3 + sp[j]) * 3;
        float h = fmaf(Wp[k * 3 + 0], pt[0],
                  fmaf(Wp[k * 3 + 1], pt[1],
                  fmaf(Wp[k * 3 + 2], pt[2], bp[k])));
        leaf[j][k] = prelu_f(h, AL);
    }
    __syncthreads();

    // ---- z2 build (smem-only) ----
    for (int i = tid; i < 5 * 768; i += NTHREADS) {
        int j = i / 768;
        int e = i - j * 768;
        unsigned d = (unsigned)e / 3u;
        int v = e - 3 * (int)d;
        zbuf[i] = leaf[2 * j + (d >> 7)][d & 127] * svec2[j][v];
    }
    __syncthreads();

    // ---- Phase B: layer-2 bilinear, weights in regs ----
    {
        const float4* zr = (const float4*)zbuf;
        float acc[5] = {0.f, 0.f, 0.f, 0.f, 0.f};
        #pragma unroll
        for (int t = 0; t < 6; t++) {
            #pragma unroll
            for (int j = 0; j < 5; j++)
                acc[j] += dot4(wB[t], zr[j * 192 + t * 32 + l]);
        }
        #pragma unroll
        for (int j = 0; j < 5; j++) {
            float r = wred(acc[j]);
            if (l == 0) g_h2[b][j][kB] = prelu_f(r + bB, A2);
        }
    }
    batch_bar(b * 4 + 0);

    // ---- load h2 (one coalesced L2 round), build z1 ----
    for (int i = tid; i < 5 * DIM; i += NTHREADS)
        h2all[i >> 7][i & 127] = g_h2[b][i >> 7][i & 127];
    __syncthreads();
    for (int i = tid; i < 2 * 768; i += NTHREADS) {
        int j = i >= 768 ? 1 : 0;
        int e = i - j * 768;
        unsigned d = (unsigned)e / 3u;
        int v = e - 3 * (int)d;
        zbuf[i] = h2all[2 * j + (d >> 7)][d & 127] * svec1[j][v];
    }
    __syncthreads();

    // ---- Phase C: layer-1 bilinear, weights in regs ----
    {
        const float4* zr = (const float4*)(zbuf + jCD * 768);
        float a0 = 0.f, a1 = 0.f;
        #pragma unroll
        for (int t = 0; t < 6; t++) {
            float4 zz = zr[t * 32 + l];
            a0 += dot4(wC0[t], zz);
            a1 += dot4(wC1[t], zz);
        }
        float r0 = wred(a0), r1 = wred(a1);
        if (l == 0)      g_tb[b][jCD][k0] = prelu_f(r0 + bC0, A1);
        else if (l == 1) g_tb[b][jCD][k1] = prelu_f(r1 + bC1, A1);
    }
    batch_bar(b * 4 + 1);

    // ---- load tb, Phase D: sample-merge linear, weights in regs ----
    for (int i = tid; i < 2 * DIM; i += NTHREADS)
        tbs[i >> 7][i & 127] = g_tb[b][i >> 7][i & 127];
    __syncthreads();
    {
        float4 xa = ((const float4*)tbs[jCD])[l];
        float4 xb = ((const float4*)leaf[10 + jCD])[l];
        float a0 = dot4(wD0[0], xa) + dot4(wD0[1], xb);
        float a1 = dot4(wD1[0], xa) + dot4(wD1[1], xb);
        float r0 = wred(a0), r1 = wred(a1);
        if (l == 0)      g_h1[b][jCD][k0] = prelu_f(r0 + bD0, A1);
        else if (l == 1) g_h1[b][jCD][k1] = prelu_f(r1 + bD1, A1);
    }
    batch_bar(b * 4 + 2);

    // ---- load h1, build z0 ----
    for (int i = tid; i < 2 * DIM; i += NTHREADS)
        h1all[i >> 7][i & 127] = g_h1[b][i >> 7][i & 127];
    __syncthreads();
    for (int e = tid; e < 768; e += NTHREADS) {
        unsigned d = (unsigned)e / 3u;
        int v = e - 3 * (int)d;
        zbuf[e] = h1all[d >> 7][d & 127] * svec0[v];
    }
    __syncthreads();

    // ---- Phase E: root bilinear, weights in regs ----
    {
        const float4* zr = (const float4*)zbuf;
        float acc = 0.f;
        #pragma unroll
        for (int t = 0; t < 6; t++)
            acc += dot4(wE[t], zr[t * 32 + l]);
        float r = wred(acc);
        if (l == 0) g_tb0[b][kB] = prelu_f(r + bE, A0);
    }
    batch_bar(b * 4 + 3);

    // ---- load tb0, Phase F: root linear, weights in regs ----
    if (tid < DIM) tb0s[tid] = g_tb0[b][tid];
    __syncthreads();
    {
        float acc = dot4(wF[0], ((const float4*)tb0s)[l]);
        acc      += dot4(wF[1], ((const float4*)h2all[4])[l]);
        float r = wred(acc);
        if (l == 0) out[(long)b * DIM + kB] = prelu_f(r + bF, A0);
    }
}

extern "C" void kernel_launch(void* const* d_in, const int* in_sizes, int n_in,
                              void* d_out, int out_size)
{
    const float* points = (const float*)d_in[0];
    const float* vec2   = (const float*)d_in[1];
    const float* vec1   = (const float*)d_in[2];
    const float* vec0   = (const float*)d_in[3];
    const float* Wp     = (const float*)d_in[4];
    const float* bp     = (const float*)d_in[5];
    const float* a_leaf = (const float*)d_in[6];
    const float* Wb2    = (const float*)d_in[7];
    const float* bb2    = (const float*)d_in[8];
    const float* a2     = (const float*)d_in[9];
    const float* Wb1    = (const float*)d_in[10];
    const float* bb1    = (const float*)d_in[11];
    const float* Ws1    = (const float*)d_in[12];
    const float* bs1    = (const float*)d_in[13];
    const float* a1     = (const float*)d_in[14];
    const float* Wb0    = (const float*)d_in[15];
    const float* bb0    = (const float*)d_in[16];
    const float* Ws0    = (const float*)d_in[17];
    const float* bs0    = (const float*)d_in[18];
    const float* a0     = (const float*)d_in[19];
    const int*   cl2    = (const int*)d_in[20];
    const int*   cr2    = (const int*)d_in[21];
    const int*   cl1    = (const int*)d_in[22];
    const int*   cr1    = (const int*)d_in[23];
    const int*   cs1    = (const int*)d_in[24];
    const int*   cl0    = (const int*)d_in[25];
    const int*   cr0    = (const int*)d_in[26];
    const int*   cs0    = (const int*)d_in[27];

    const int B  = out_size / DIM;          // 8
    const int N3 = in_sizes[0] / (3 * B);   // 131072
    const int N2 = in_sizes[1] / (3 * B);   // 65536
    const int N1 = in_sizes[2] / (3 * B);   // 1024

    encoder_fused_kernel<<<B * NSLICE, NTHREADS>>>(
        points, vec2, vec1, vec0,
        Wp, bp, a_leaf, Wb2, bb2, a2,
        Wb1, bb1, Ws1, bs1, a1,
        Wb0, bb0, Ws0, bs0, a0,
        cl2, cr2, cl1, cr1, cs1, cl0, cr0, cs0,
        (float*)d_out, N3, N2, N1);
}